// round 14
// baseline (speedup 1.0000x reference)
#include <cuda_runtime.h>
#include <cuda_fp16.h>
#include <cstdint>

// ---------------------------------------------------------------------------
// Problem constants
// ---------------------------------------------------------------------------
#define TOKENS 8192
#define IN_F   3072
#define OUT_F  8192
#define GROUP  128

// GEMM tiling: 128x256 CTA tile, 8 warps (2M x 4N, warp tile 64x64),
// 4-stage bulk pipeline, fragment double-buffering, per-warp k-step rotation,
// persistent CTAs (division-free bookkeeping, cross-tile prefetch).
// Round 14: bias pre-loaded into accumulator init -> epilogue is pure stores.
#define MT 128
#define NT 256
#define KC 64
#define NKC (IN_F / KC)          // 48
#define STAGES 4
#define A_TILE_BYTES (MT * 128)  // 16384
#define B_TILE_BYTES (NT * 128)  // 32768
#define STAGE_BYTES (A_TILE_BYTES + B_TILE_BYTES)   // 49152
#define SMEM_REQ (1024 + STAGES * STAGE_BYTES + 1024)  // ~198KB, 1 CTA/SM

#define MTILES (TOKENS / MT)     // 64
#define NTILES (OUT_F / NT)      // 32
#define NT_TOTAL (MTILES * NTILES)  // 2048

#define XBLOCKS ((TOKENS * (IN_F / 8)) / 256)   // 12288
#define WBLOCKS ((OUT_F * (IN_F / 8)) / 256)    // 12288

// ---------------------------------------------------------------------------
// Static device scratch: pre-tiled, pre-SW128-swizzled fp16 operands.
// ---------------------------------------------------------------------------
__device__ __align__(1024) __half g_X[(size_t)TOKENS * IN_F];
__device__ __align__(1024) __half g_W[(size_t)OUT_F * IN_F];

__device__ __forceinline__ uint32_t swz128(uint32_t b) { return b ^ ((b >> 3) & 0x70); }

// ---------------------------------------------------------------------------
// Fused preprocess: first XBLOCKS blocks convert x, rest dequantize W.
// ---------------------------------------------------------------------------
__global__ void preproc_kernel(const float* __restrict__ x,
                               const int* __restrict__ pk,
                               const float* __restrict__ sc) {
    uint32_t b = blockIdx.x;
    if (b < XBLOCKS) {
        uint32_t idx = b * blockDim.x + threadIdx.x;
        uint32_t m = idx / (IN_F / 8);
        uint32_t g = idx % (IN_F / 8);
        const float4* src = reinterpret_cast<const float4*>(x + (size_t)m * IN_F + (size_t)g * 8);
        float4 a = __ldcs(src);
        float4 c = __ldcs(src + 1);
        __half2 h0 = __floats2half2_rn(a.x, a.y);
        __half2 h1 = __floats2half2_rn(a.z, a.w);
        __half2 h2 = __floats2half2_rn(c.x, c.y);
        __half2 h3 = __floats2half2_rn(c.z, c.w);
        uint4 v;
        v.x = *reinterpret_cast<uint32_t*>(&h0);
        v.y = *reinterpret_cast<uint32_t*>(&h1);
        v.z = *reinterpret_cast<uint32_t*>(&h2);
        v.w = *reinterpret_cast<uint32_t*>(&h3);
        uint32_t t = m / MT, r = m % MT, cc = g / 8, kk = (g % 8) * 8;
        char* base = reinterpret_cast<char*>(g_X) + ((size_t)t * NKC + cc) * A_TILE_BYTES;
        __stcs(reinterpret_cast<uint4*>(base + swz128(r * 128 + kk * 2)), v);
    } else {
        uint32_t idx = (b - XBLOCKS) * blockDim.x + threadIdx.x;
        uint32_t o = idx / (IN_F / 8);
        uint32_t g = idx % (IN_F / 8);
        uint4 p = __ldcs(reinterpret_cast<const uint4*>(pk + (size_t)o * (IN_F / 2) + (size_t)g * 4));
        float s = __ldg(sc + (size_t)o * (IN_F / GROUP) + (g / 16));
        uint32_t w[4] = {p.x, p.y, p.z, p.w};
        uint32_t res[4];
#pragma unroll
        for (int i = 0; i < 4; i++) {
            uint32_t byte = w[i] & 0xFFu;
            int ev = (int)((byte & 15u) ^ 8u) - 8;
            int od = (int)(((byte >> 4) & 15u) ^ 8u) - 8;
            __half2 h = __floats2half2_rn(s * (float)ev, s * (float)od);
            res[i] = *reinterpret_cast<uint32_t*>(&h);
        }
        uint4 v; v.x = res[0]; v.y = res[1]; v.z = res[2]; v.w = res[3];
        uint32_t t = o / NT, r = o % NT, cc = g / 8, kk = (g % 8) * 8;
        char* base = reinterpret_cast<char*>(g_W) + ((size_t)t * NKC + cc) * B_TILE_BYTES;
        __stcs(reinterpret_cast<uint4*>(base + swz128(r * 128 + kk * 2)), v);
    }
}

// ---------------------------------------------------------------------------
// PTX helpers
// ---------------------------------------------------------------------------
__device__ __forceinline__ uint32_t smem_u32(const void* p) {
    uint32_t a;
    asm("{ .reg .u64 t; cvta.to.shared.u64 t, %1; cvt.u32.u64 %0, t; }" : "=r"(a) : "l"(p));
    return a;
}
#define MBAR_INIT(a, c) \
    asm volatile("mbarrier.init.shared.b64 [%0], %1;" :: "r"(a), "r"(c) : "memory")
#define MBAR_EXPECT_TX(a, n) \
    asm volatile("mbarrier.arrive.expect_tx.shared.b64 _, [%0], %1;" :: "r"(a), "r"(n) : "memory")
#define MBAR_ARRIVE(a) \
    asm volatile("mbarrier.arrive.shared.b64 _, [%0];" :: "r"(a) : "memory")
#define MBAR_WAIT(addr, ph) do {                                                        \
    uint32_t _m = (addr); uint32_t _p = (ph); uint32_t _d;                              \
    asm volatile("{\n\t.reg .pred p;\n\t"                                               \
        "mbarrier.try_wait.parity.acquire.cta.shared::cta.b64 p, [%1], %2;\n\t"         \
        "selp.b32 %0, 1, 0, p;\n\t}"                                                    \
        : "=r"(_d) : "r"(_m), "r"(_p) : "memory");                                      \
    if (!_d) {                                                                          \
        asm volatile("{\n\t.reg .pred P1;\n\t"                                          \
            "WL%=:\n\t"                                                                 \
            "mbarrier.try_wait.parity.acquire.cta.shared::cta.b64 P1, [%0], %1, 0x989680;\n\t" \
            "@P1 bra.uni WD%=;\n\t"                                                     \
            "bra.uni WL%=;\n\t"                                                         \
            "WD%=:\n\t}"                                                                \
            :: "r"(_m), "r"(_p) : "memory");                                            \
    }                                                                                   \
} while (0)

__device__ __forceinline__ void bulk_g2s(uint32_t dst, const void* src, uint32_t bytes, uint32_t mbar) {
    asm volatile(
        "cp.async.bulk.shared::cluster.global.mbarrier::complete_tx::bytes [%0], [%1], %2, [%3];"
        :: "r"(dst), "l"(src), "r"(bytes), "r"(mbar) : "memory");
}

#define LDSM_X4(R, addr)                                                               \
    asm volatile("ldmatrix.sync.aligned.m8n8.x4.shared.b16 {%0,%1,%2,%3}, [%4];"       \
        : "=r"((R)[0]), "=r"((R)[1]), "=r"((R)[2]), "=r"((R)[3]) : "r"(addr))

#define MMA16816(C, A, B0, B1)                                                          \
    asm volatile("mma.sync.aligned.m16n8k16.row.col.f32.f16.f16.f32 "                   \
        "{%0,%1,%2,%3}, {%4,%5,%6,%7}, {%8,%9}, {%0,%1,%2,%3};"                         \
        : "+f"((C)[0]), "+f"((C)[1]), "+f"((C)[2]), "+f"((C)[3])                        \
        : "r"((A)[0]), "r"((A)[1]), "r"((A)[2]), "r"((A)[3]), "r"(B0), "r"(B1))

// ---------------------------------------------------------------------------
// Persistent GEMM: grid = #SMs; division-free bookkeeping; cross-tile
// prefetch; bias preloaded into accumulators (epilogue = pure stores).
// ---------------------------------------------------------------------------
__global__ void __launch_bounds__(256, 1) gemm_kernel(float* __restrict__ out,
                                                      const float* __restrict__ bias) {
    extern __shared__ char smem_raw[];
    char* sbp = (char*)(((uintptr_t)smem_raw + 1023) & ~(uintptr_t)1023);
    const uint32_t SB  = smem_u32(sbp);
    const uint32_t BAR = SB + STAGES * STAGE_BYTES;      // full[s]@+16s, empty[s]@+16s+8

    const int tid = threadIdx.x;
    const int wid = tid >> 5;
    const int lid = tid & 31;
    const int wm = wid >> 2;
    const int wn = wid & 3;
    const uint32_t kph = (uint32_t)(wm * 2);

    const int bid = blockIdx.x;
    const int G   = gridDim.x;
    const int my_n = (NT_TOTAL - bid + G - 1) / G;
    if (my_n <= 0) return;
    const int L = my_n * NKC;

    if (tid == 0) {
#pragma unroll
        for (int s = 0; s < STAGES; s++) {
            MBAR_INIT(BAR + s * 16, 1);      // full: expect_tx arrive + tx
            MBAR_INIT(BAR + s * 16 + 8, 8);  // empty: one arrive per warp
        }
    }
    __syncthreads();

    // ---- incremental tile decode state (supertile raster: 16m x 32n) ----
    int csr = bid >> 9, crem = bid & 511;
    int psr = csr, prem = crem;
    int cq_p = STAGES - 1;
    const char* pA_base = (const char*)g_X +
        (size_t)((psr << 4) | (prem & 15)) * NKC * A_TILE_BYTES;
    const char* pB_base = (const char*)g_W +
        (size_t)(prem >> 4) * NKC * B_TILE_BYTES;

    // prologue: fill local chunks 0..2
    if (tid == 0) {
#pragma unroll
        for (int c = 0; c < STAGES - 1; c++) {
            MBAR_EXPECT_TX(BAR + c * 16, (uint32_t)STAGE_BYTES);
            bulk_g2s(SB + c * STAGE_BYTES, pA_base + (size_t)c * A_TILE_BYTES,
                     A_TILE_BYTES, BAR + c * 16);
            bulk_g2s(SB + c * STAGE_BYTES + A_TILE_BYTES,
                     pB_base + (size_t)c * B_TILE_BYTES,
                     B_TILE_BYTES, BAR + c * 16);
        }
    }

    // per-thread ldmatrix address components
    const int l16 = lid & 15;
    const uint32_t half16 = (uint32_t)(lid >> 4) * 16;
    uint32_t arow[4], axm[4], brow[4], bxm[4];
#pragma unroll
    for (int i = 0; i < 4; i++) {
        uint32_t ra = (uint32_t)(wm * 64 + i * 16 + l16);
        arow[i] = ra * 128;
        axm[i] = (ra & 7) << 4;
        uint32_t rb = (uint32_t)(wn * 64 + i * 16 + l16);
        brow[i] = rb * 128;
        bxm[i] = (rb & 7) << 4;
    }

    uint32_t a[2][4][4], b[2][4][4];
    int g = 0;

    // initial fragment prefetch: stage 0, k-step kph, into buf 0
    MBAR_WAIT(BAR + 0, 0);
    {
        const uint32_t As = SB, Bs = SB + A_TILE_BYTES;
        const uint32_t kb = kph * 32 + half16;
#pragma unroll
        for (int mi = 0; mi < 4; mi++) LDSM_X4(a[0][mi], As + arow[mi] + (kb ^ axm[mi]));
#pragma unroll
        for (int nj = 0; nj < 4; nj++) LDSM_X4(b[0][nj], Bs + brow[nj] + (kb ^ bxm[nj]));
    }

    const int row_in_tile = lid >> 2;
    const int col_pair = (lid & 3) * 2;

    for (int tile_iter = 0; tile_iter < my_n; tile_iter++) {
        const int m_tile = (csr << 4) | (crem & 15);
        const int n_tile = crem >> 4;
        const size_t nbase = (size_t)n_tile * NT;

        // bias preload -> accumulator init (HMMA accumulates on top).
        // These 16 LDGs overlap the pipelined mainloop; the epilogue loses
        // 64 LDG + 128 FADD per thread.
        float acc[4][8][4];
#pragma unroll
        for (int ni = 0; ni < 8; ni++) {
            const int nloc = wn * 64 + ni * 8 + col_pair;
            const float b0 = __ldg(bias + nbase + nloc);
            const float b1 = __ldg(bias + nbase + nloc + 1);
#pragma unroll
            for (int mi = 0; mi < 4; mi++) {
                acc[mi][ni][0] = b0;
                acc[mi][ni][1] = b1;
                acc[mi][ni][2] = b0;
                acc[mi][ni][3] = b1;
            }
        }

        for (int c = 0; c < NKC; c++, g++) {
            const int s = g & 3;
            const uint32_t As = SB + s * STAGE_BYTES;
            const uint32_t Bs = As + A_TILE_BYTES;
            const int s2 = (g + 1) & 3;

#pragma unroll
            for (int j = 0; j < 4; j++) {
                const int cur = j & 1, nxt = cur ^ 1;
                if (j < 3) {
                    const uint32_t kq = (uint32_t)((j + 1 + kph) & 3);
                    const uint32_t kb = kq * 32 + half16;
#pragma unroll
                    for (int mi = 0; mi < 4; mi++) LDSM_X4(a[nxt][mi], As + arow[mi] + (kb ^ axm[mi]));
#pragma unroll
                    for (int nj = 0; nj < 4; nj++) LDSM_X4(b[nxt][nj], Bs + brow[nj] + (kb ^ bxm[nj]));
                } else if (g + 1 < L) {
                    MBAR_WAIT(BAR + s2 * 16, (uint32_t)(((g + 1) >> 2) & 1));
                    const uint32_t As2 = SB + s2 * STAGE_BYTES;
                    const uint32_t Bs2 = As2 + A_TILE_BYTES;
                    const uint32_t kb = kph * 32 + half16;
#pragma unroll
                    for (int mi = 0; mi < 4; mi++) LDSM_X4(a[nxt][mi], As2 + arow[mi] + (kb ^ axm[mi]));
#pragma unroll
                    for (int nj = 0; nj < 4; nj++) LDSM_X4(b[nxt][nj], Bs2 + brow[nj] + (kb ^ bxm[nj]));
                }
#pragma unroll
                for (int mi = 0; mi < 4; mi++) {
#pragma unroll
                    for (int nj = 0; nj < 4; nj++) {
                        MMA16816(acc[mi][2 * nj],     a[cur][mi], b[cur][nj][0], b[cur][nj][2]);
                        MMA16816(acc[mi][2 * nj + 1], a[cur][mi], b[cur][nj][1], b[cur][nj][3]);
                    }
                }
            }

            if (lid == 0) MBAR_ARRIVE(BAR + s * 16 + 8);

            if (wid == (g & 7) && lid == 0 && g + STAGES - 1 < L) {
                const int sp = (g + STAGES - 1) & 3;
                if (g >= 1) MBAR_WAIT(BAR + sp * 16 + 8, (uint32_t)(((g - 1) >> 2) & 1));
                MBAR_EXPECT_TX(BAR + sp * 16, (uint32_t)STAGE_BYTES);
                bulk_g2s(SB + sp * STAGE_BYTES,
                         pA_base + (size_t)cq_p * A_TILE_BYTES,
                         A_TILE_BYTES, BAR + sp * 16);
                bulk_g2s(SB + sp * STAGE_BYTES + A_TILE_BYTES,
                         pB_base + (size_t)cq_p * B_TILE_BYTES,
                         B_TILE_BYTES, BAR + sp * 16);
            }
            if (++cq_p == NKC) {
                cq_p = 0;
                prem += G;
                if (prem >= 512) { prem -= 512; psr++; }
                pA_base = (const char*)g_X +
                    (size_t)((psr << 4) | (prem & 15)) * NKC * A_TILE_BYTES;
                pB_base = (const char*)g_W +
                    (size_t)(prem >> 4) * NKC * B_TILE_BYTES;
            }
        }

        // epilogue: pure stores (bias already inside acc); overlaps next
        // tile's in-flight fragment loads + producer bulk copies.
        const size_t mbase = (size_t)m_tile * MT + wm * 64;
#pragma unroll
        for (int mi = 0; mi < 4; mi++) {
            const size_t m0 = mbase + mi * 16 + row_in_tile;
#pragma unroll
            for (int ni = 0; ni < 8; ni++) {
                const int nloc = wn * 64 + ni * 8 + col_pair;
                float2 v0 = make_float2(acc[mi][ni][0], acc[mi][ni][1]);
                float2 v1 = make_float2(acc[mi][ni][2], acc[mi][ni][3]);
                __stcs(reinterpret_cast<float2*>(out + m0 * OUT_F + nbase + nloc), v0);
                __stcs(reinterpret_cast<float2*>(out + (m0 + 8) * OUT_F + nbase + nloc), v1);
            }
        }

        crem += G;
        if (crem >= 512) { crem -= 512; csr++; }
    }
}

// ---------------------------------------------------------------------------
// Launch
// ---------------------------------------------------------------------------
extern "C" void kernel_launch(void* const* d_in, const int* in_sizes, int n_in,
                              void* d_out, int out_size) {
    (void)in_sizes; (void)n_in; (void)out_size;
    const float* x    = (const float*)d_in[0];
    const int*   pk   = (const int*)d_in[1];
    const float* sc   = (const float*)d_in[2];
    const float* bias = (const float*)d_in[3];
    float* out = (float*)d_out;

    cudaFuncSetAttribute(gemm_kernel, cudaFuncAttributeMaxDynamicSharedMemorySize, SMEM_REQ);

    int nsm = 148;
    cudaDeviceGetAttribute(&nsm, cudaDevAttrMultiProcessorCount, 0);
    if (nsm <= 0 || nsm > NT_TOTAL) nsm = 148;

    preproc_kernel<<<XBLOCKS + WBLOCKS, 256>>>(x, pk, sc);
    gemm_kernel<<<nsm, 256, SMEM_REQ>>>(out, bias);
}

// round 15
// speedup vs baseline: 1.1119x; 1.1119x over previous
#include <cuda_runtime.h>
#include <cuda_fp16.h>
#include <cstdint>

// ---------------------------------------------------------------------------
// Problem constants
// ---------------------------------------------------------------------------
#define TOKENS 8192
#define IN_F   3072
#define OUT_F  8192
#define GROUP  128

// GEMM tiling: 128x256 CTA tile, 8 warps (2M x 4N, warp tile 64x64),
// 4-stage bulk pipeline, fragment double-buffering, per-warp k-step rotation,
// persistent CTAs (division-free bookkeeping, cross-tile prefetch).
// Round 15: R13 champion + hoisted float2 bias loads at epilogue start
// (acc init back to 0 -> no load dependency ahead of the MMA stream).
#define MT 128
#define NT 256
#define KC 64
#define NKC (IN_F / KC)          // 48
#define STAGES 4
#define A_TILE_BYTES (MT * 128)  // 16384
#define B_TILE_BYTES (NT * 128)  // 32768
#define STAGE_BYTES (A_TILE_BYTES + B_TILE_BYTES)   // 49152
#define SMEM_REQ (1024 + STAGES * STAGE_BYTES + 1024)  // ~198KB, 1 CTA/SM

#define MTILES (TOKENS / MT)     // 64
#define NTILES (OUT_F / NT)      // 32
#define NT_TOTAL (MTILES * NTILES)  // 2048

#define XBLOCKS ((TOKENS * (IN_F / 8)) / 256)   // 12288
#define WBLOCKS ((OUT_F * (IN_F / 8)) / 256)    // 12288

// ---------------------------------------------------------------------------
// Static device scratch: pre-tiled, pre-SW128-swizzled fp16 operands.
// ---------------------------------------------------------------------------
__device__ __align__(1024) __half g_X[(size_t)TOKENS * IN_F];
__device__ __align__(1024) __half g_W[(size_t)OUT_F * IN_F];

__device__ __forceinline__ uint32_t swz128(uint32_t b) { return b ^ ((b >> 3) & 0x70); }

// ---------------------------------------------------------------------------
// Fused preprocess: first XBLOCKS blocks convert x, rest dequantize W.
// ---------------------------------------------------------------------------
__global__ void preproc_kernel(const float* __restrict__ x,
                               const int* __restrict__ pk,
                               const float* __restrict__ sc) {
    uint32_t b = blockIdx.x;
    if (b < XBLOCKS) {
        uint32_t idx = b * blockDim.x + threadIdx.x;
        uint32_t m = idx / (IN_F / 8);
        uint32_t g = idx % (IN_F / 8);
        const float4* src = reinterpret_cast<const float4*>(x + (size_t)m * IN_F + (size_t)g * 8);
        float4 a = __ldcs(src);
        float4 c = __ldcs(src + 1);
        __half2 h0 = __floats2half2_rn(a.x, a.y);
        __half2 h1 = __floats2half2_rn(a.z, a.w);
        __half2 h2 = __floats2half2_rn(c.x, c.y);
        __half2 h3 = __floats2half2_rn(c.z, c.w);
        uint4 v;
        v.x = *reinterpret_cast<uint32_t*>(&h0);
        v.y = *reinterpret_cast<uint32_t*>(&h1);
        v.z = *reinterpret_cast<uint32_t*>(&h2);
        v.w = *reinterpret_cast<uint32_t*>(&h3);
        uint32_t t = m / MT, r = m % MT, cc = g / 8, kk = (g % 8) * 8;
        char* base = reinterpret_cast<char*>(g_X) + ((size_t)t * NKC + cc) * A_TILE_BYTES;
        __stcs(reinterpret_cast<uint4*>(base + swz128(r * 128 + kk * 2)), v);
    } else {
        uint32_t idx = (b - XBLOCKS) * blockDim.x + threadIdx.x;
        uint32_t o = idx / (IN_F / 8);
        uint32_t g = idx % (IN_F / 8);
        uint4 p = __ldcs(reinterpret_cast<const uint4*>(pk + (size_t)o * (IN_F / 2) + (size_t)g * 4));
        float s = __ldg(sc + (size_t)o * (IN_F / GROUP) + (g / 16));
        uint32_t w[4] = {p.x, p.y, p.z, p.w};
        uint32_t res[4];
#pragma unroll
        for (int i = 0; i < 4; i++) {
            uint32_t byte = w[i] & 0xFFu;
            int ev = (int)((byte & 15u) ^ 8u) - 8;
            int od = (int)(((byte >> 4) & 15u) ^ 8u) - 8;
            __half2 h = __floats2half2_rn(s * (float)ev, s * (float)od);
            res[i] = *reinterpret_cast<uint32_t*>(&h);
        }
        uint4 v; v.x = res[0]; v.y = res[1]; v.z = res[2]; v.w = res[3];
        uint32_t t = o / NT, r = o % NT, cc = g / 8, kk = (g % 8) * 8;
        char* base = reinterpret_cast<char*>(g_W) + ((size_t)t * NKC + cc) * B_TILE_BYTES;
        __stcs(reinterpret_cast<uint4*>(base + swz128(r * 128 + kk * 2)), v);
    }
}

// ---------------------------------------------------------------------------
// PTX helpers
// ---------------------------------------------------------------------------
__device__ __forceinline__ uint32_t smem_u32(const void* p) {
    uint32_t a;
    asm("{ .reg .u64 t; cvta.to.shared.u64 t, %1; cvt.u32.u64 %0, t; }" : "=r"(a) : "l"(p));
    return a;
}
#define MBAR_INIT(a, c) \
    asm volatile("mbarrier.init.shared.b64 [%0], %1;" :: "r"(a), "r"(c) : "memory")
#define MBAR_EXPECT_TX(a, n) \
    asm volatile("mbarrier.arrive.expect_tx.shared.b64 _, [%0], %1;" :: "r"(a), "r"(n) : "memory")
#define MBAR_ARRIVE(a) \
    asm volatile("mbarrier.arrive.shared.b64 _, [%0];" :: "r"(a) : "memory")
#define MBAR_WAIT(addr, ph) do {                                                        \
    uint32_t _m = (addr); uint32_t _p = (ph); uint32_t _d;                              \
    asm volatile("{\n\t.reg .pred p;\n\t"                                               \
        "mbarrier.try_wait.parity.acquire.cta.shared::cta.b64 p, [%1], %2;\n\t"         \
        "selp.b32 %0, 1, 0, p;\n\t}"                                                    \
        : "=r"(_d) : "r"(_m), "r"(_p) : "memory");                                      \
    if (!_d) {                                                                          \
        asm volatile("{\n\t.reg .pred P1;\n\t"                                          \
            "WL%=:\n\t"                                                                 \
            "mbarrier.try_wait.parity.acquire.cta.shared::cta.b64 P1, [%0], %1, 0x989680;\n\t" \
            "@P1 bra.uni WD%=;\n\t"                                                     \
            "bra.uni WL%=;\n\t"                                                         \
            "WD%=:\n\t}"                                                                \
            :: "r"(_m), "r"(_p) : "memory");                                            \
    }                                                                                   \
} while (0)

__device__ __forceinline__ void bulk_g2s(uint32_t dst, const void* src, uint32_t bytes, uint32_t mbar) {
    asm volatile(
        "cp.async.bulk.shared::cluster.global.mbarrier::complete_tx::bytes [%0], [%1], %2, [%3];"
        :: "r"(dst), "l"(src), "r"(bytes), "r"(mbar) : "memory");
}

#define LDSM_X4(R, addr)                                                               \
    asm volatile("ldmatrix.sync.aligned.m8n8.x4.shared.b16 {%0,%1,%2,%3}, [%4];"       \
        : "=r"((R)[0]), "=r"((R)[1]), "=r"((R)[2]), "=r"((R)[3]) : "r"(addr))

#define MMA16816(C, A, B0, B1)                                                          \
    asm volatile("mma.sync.aligned.m16n8k16.row.col.f32.f16.f16.f32 "                   \
        "{%0,%1,%2,%3}, {%4,%5,%6,%7}, {%8,%9}, {%0,%1,%2,%3};"                         \
        : "+f"((C)[0]), "+f"((C)[1]), "+f"((C)[2]), "+f"((C)[3])                        \
        : "r"((A)[0]), "r"((A)[1]), "r"((A)[2]), "r"((A)[3]), "r"(B0), "r"(B1))

// ---------------------------------------------------------------------------
// Persistent GEMM (R13 structure): grid = #SMs; division-free bookkeeping;
// cross-tile prefetch; epilogue with hoisted float2 bias loads.
// ---------------------------------------------------------------------------
__global__ void __launch_bounds__(256, 1) gemm_kernel(float* __restrict__ out,
                                                      const float* __restrict__ bias) {
    extern __shared__ char smem_raw[];
    char* sbp = (char*)(((uintptr_t)smem_raw + 1023) & ~(uintptr_t)1023);
    const uint32_t SB  = smem_u32(sbp);
    const uint32_t BAR = SB + STAGES * STAGE_BYTES;      // full[s]@+16s, empty[s]@+16s+8

    const int tid = threadIdx.x;
    const int wid = tid >> 5;
    const int lid = tid & 31;
    const int wm = wid >> 2;
    const int wn = wid & 3;
    const uint32_t kph = (uint32_t)(wm * 2);

    const int bid = blockIdx.x;
    const int G   = gridDim.x;
    const int my_n = (NT_TOTAL - bid + G - 1) / G;
    if (my_n <= 0) return;
    const int L = my_n * NKC;

    if (tid == 0) {
#pragma unroll
        for (int s = 0; s < STAGES; s++) {
            MBAR_INIT(BAR + s * 16, 1);      // full: expect_tx arrive + tx
            MBAR_INIT(BAR + s * 16 + 8, 8);  // empty: one arrive per warp
        }
    }
    __syncthreads();

    // ---- incremental tile decode state (supertile raster: 16m x 32n) ----
    int csr = bid >> 9, crem = bid & 511;
    int psr = csr, prem = crem;
    int cq_p = STAGES - 1;
    const char* pA_base = (const char*)g_X +
        (size_t)((psr << 4) | (prem & 15)) * NKC * A_TILE_BYTES;
    const char* pB_base = (const char*)g_W +
        (size_t)(prem >> 4) * NKC * B_TILE_BYTES;

    // prologue: fill local chunks 0..2
    if (tid == 0) {
#pragma unroll
        for (int c = 0; c < STAGES - 1; c++) {
            MBAR_EXPECT_TX(BAR + c * 16, (uint32_t)STAGE_BYTES);
            bulk_g2s(SB + c * STAGE_BYTES, pA_base + (size_t)c * A_TILE_BYTES,
                     A_TILE_BYTES, BAR + c * 16);
            bulk_g2s(SB + c * STAGE_BYTES + A_TILE_BYTES,
                     pB_base + (size_t)c * B_TILE_BYTES,
                     B_TILE_BYTES, BAR + c * 16);
        }
    }

    // per-thread ldmatrix address components
    const int l16 = lid & 15;
    const uint32_t half16 = (uint32_t)(lid >> 4) * 16;
    uint32_t arow[4], axm[4], brow[4], bxm[4];
#pragma unroll
    for (int i = 0; i < 4; i++) {
        uint32_t ra = (uint32_t)(wm * 64 + i * 16 + l16);
        arow[i] = ra * 128;
        axm[i] = (ra & 7) << 4;
        uint32_t rb = (uint32_t)(wn * 64 + i * 16 + l16);
        brow[i] = rb * 128;
        bxm[i] = (rb & 7) << 4;
    }

    uint32_t a[2][4][4], b[2][4][4];
    int g = 0;

    // initial fragment prefetch: stage 0, k-step kph, into buf 0
    MBAR_WAIT(BAR + 0, 0);
    {
        const uint32_t As = SB, Bs = SB + A_TILE_BYTES;
        const uint32_t kb = kph * 32 + half16;
#pragma unroll
        for (int mi = 0; mi < 4; mi++) LDSM_X4(a[0][mi], As + arow[mi] + (kb ^ axm[mi]));
#pragma unroll
        for (int nj = 0; nj < 4; nj++) LDSM_X4(b[0][nj], Bs + brow[nj] + (kb ^ bxm[nj]));
    }

    const int row_in_tile = lid >> 2;
    const int col_pair = (lid & 3) * 2;

    for (int tile_iter = 0; tile_iter < my_n; tile_iter++) {
        const int m_tile = (csr << 4) | (crem & 15);
        const int n_tile = crem >> 4;
        const size_t nbase = (size_t)n_tile * NT;

        float acc[4][8][4];
#pragma unroll
        for (int mi = 0; mi < 4; mi++)
#pragma unroll
            for (int ni = 0; ni < 8; ni++)
#pragma unroll
                for (int q = 0; q < 4; q++) acc[mi][ni][q] = 0.0f;

        for (int c = 0; c < NKC; c++, g++) {
            const int s = g & 3;
            const uint32_t As = SB + s * STAGE_BYTES;
            const uint32_t Bs = As + A_TILE_BYTES;
            const int s2 = (g + 1) & 3;

#pragma unroll
            for (int j = 0; j < 4; j++) {
                const int cur = j & 1, nxt = cur ^ 1;
                if (j < 3) {
                    const uint32_t kq = (uint32_t)((j + 1 + kph) & 3);
                    const uint32_t kb = kq * 32 + half16;
#pragma unroll
                    for (int mi = 0; mi < 4; mi++) LDSM_X4(a[nxt][mi], As + arow[mi] + (kb ^ axm[mi]));
#pragma unroll
                    for (int nj = 0; nj < 4; nj++) LDSM_X4(b[nxt][nj], Bs + brow[nj] + (kb ^ bxm[nj]));
                } else if (g + 1 < L) {
                    // uniform cross-chunk / cross-TILE prefetch
                    MBAR_WAIT(BAR + s2 * 16, (uint32_t)(((g + 1) >> 2) & 1));
                    const uint32_t As2 = SB + s2 * STAGE_BYTES;
                    const uint32_t Bs2 = As2 + A_TILE_BYTES;
                    const uint32_t kb = kph * 32 + half16;
#pragma unroll
                    for (int mi = 0; mi < 4; mi++) LDSM_X4(a[nxt][mi], As2 + arow[mi] + (kb ^ axm[mi]));
#pragma unroll
                    for (int nj = 0; nj < 4; nj++) LDSM_X4(b[nxt][nj], Bs2 + brow[nj] + (kb ^ bxm[nj]));
                }
#pragma unroll
                for (int mi = 0; mi < 4; mi++) {
#pragma unroll
                    for (int nj = 0; nj < 4; nj++) {
                        MMA16816(acc[mi][2 * nj],     a[cur][mi], b[cur][nj][0], b[cur][nj][2]);
                        MMA16816(acc[mi][2 * nj + 1], a[cur][mi], b[cur][nj][1], b[cur][nj][3]);
                    }
                }
            }

            if (lid == 0) MBAR_ARRIVE(BAR + s * 16 + 8);

            if (wid == (g & 7) && lid == 0 && g + STAGES - 1 < L) {
                const int sp = (g + STAGES - 1) & 3;
                if (g >= 1) MBAR_WAIT(BAR + sp * 16 + 8, (uint32_t)(((g - 1) >> 2) & 1));
                MBAR_EXPECT_TX(BAR + sp * 16, (uint32_t)STAGE_BYTES);
                bulk_g2s(SB + sp * STAGE_BYTES,
                         pA_base + (size_t)cq_p * A_TILE_BYTES,
                         A_TILE_BYTES, BAR + sp * 16);
                bulk_g2s(SB + sp * STAGE_BYTES + A_TILE_BYTES,
                         pB_base + (size_t)cq_p * B_TILE_BYTES,
                         B_TILE_BYTES, BAR + sp * 16);
            }
            if (++cq_p == NKC) {
                cq_p = 0;
                prem += G;
                if (prem >= 512) { prem -= 512; psr++; }
                pA_base = (const char*)g_X +
                    (size_t)((psr << 4) | (prem & 15)) * NKC * A_TILE_BYTES;
                pB_base = (const char*)g_W +
                    (size_t)(prem >> 4) * NKC * B_TILE_BYTES;
            }
        }

        // epilogue: hoisted float2 bias loads (8 LDG.64 issued back-to-back,
        // latency overlapped under MLP), then add+store. Overlaps next tile's
        // in-flight fragment loads + producer bulk copies.
        const size_t mbase = (size_t)m_tile * MT + wm * 64;
        float2 bsv[8];
#pragma unroll
        for (int ni = 0; ni < 8; ni++) {
            const int nloc = wn * 64 + ni * 8 + col_pair;
            bsv[ni] = __ldg(reinterpret_cast<const float2*>(bias + nbase + nloc));
        }
#pragma unroll
        for (int mi = 0; mi < 4; mi++) {
            const size_t m0 = mbase + mi * 16 + row_in_tile;
#pragma unroll
            for (int ni = 0; ni < 8; ni++) {
                const int nloc = wn * 64 + ni * 8 + col_pair;
                float2 v0 = make_float2(acc[mi][ni][0] + bsv[ni].x,
                                        acc[mi][ni][1] + bsv[ni].y);
                float2 v1 = make_float2(acc[mi][ni][2] + bsv[ni].x,
                                        acc[mi][ni][3] + bsv[ni].y);
                __stcs(reinterpret_cast<float2*>(out + m0 * OUT_F + nbase + nloc), v0);
                __stcs(reinterpret_cast<float2*>(out + (m0 + 8) * OUT_F + nbase + nloc), v1);
            }
        }

        crem += G;
        if (crem >= 512) { crem -= 512; csr++; }
    }
}

// ---------------------------------------------------------------------------
// Launch
// ---------------------------------------------------------------------------
extern "C" void kernel_launch(void* const* d_in, const int* in_sizes, int n_in,
                              void* d_out, int out_size) {
    (void)in_sizes; (void)n_in; (void)out_size;
    const float* x    = (const float*)d_in[0];
    const int*   pk   = (const int*)d_in[1];
    const float* sc   = (const float*)d_in[2];
    const float* bias = (const float*)d_in[3];
    float* out = (float*)d_out;

    cudaFuncSetAttribute(gemm_kernel, cudaFuncAttributeMaxDynamicSharedMemorySize, SMEM_REQ);

    int nsm = 148;
    cudaDeviceGetAttribute(&nsm, cudaDevAttrMultiProcessorCount, 0);
    if (nsm <= 0 || nsm > NT_TOTAL) nsm = 148;

    preproc_kernel<<<XBLOCKS + WBLOCKS, 256>>>(x, pk, sc);
    gemm_kernel<<<nsm, 256, SMEM_REQ>>>(out, bias);
}